// round 1
// baseline (speedup 1.0000x reference)
#include <cuda_runtime.h>

// Problem constants (fixed shapes per reference)
#define NB   16384        // batch
#define DD   512          // D
#define N1C  1024         // 2D  (gemm1 output cols)
#define K1C  512          // gemm1 K (t folded into bias)
#define N2C  512          // gemm2 output cols
#define K2C  1024         // gemm2 K (t folded into bias)

// Scratch in device globals (no allocations allowed)
__device__ float g_W1p[N1C * K1C];                 // 2 MB, dense repack of W1[:, :512]
__device__ float g_W2p[N2C * K2C];                 // 2 MB, dense repack of W2[:, :1024]
__device__ float g_beff1[N1C];                     // b1 + t*W1[:,512]
__device__ float g_beff2[N2C];                     // b2 + t*W2[:,1024]
__device__ float g_c[N1C];                         // c[j] = sum_k W2[k,j]*W1[j,k]
__device__ float g_h[(long long)NB * N1C];         // 64 MB relu activations

// ---------------------------------------------------------------------------
// Prep: repack weights to dense aligned layout
// ---------------------------------------------------------------------------
__global__ void prep_pack(const float* __restrict__ W1, const float* __restrict__ W2) {
    int idx = blockIdx.x * 256 + threadIdx.x;
    if (idx < N1C * K1C) {
        int n = idx >> 9;          // /512
        int k = idx & 511;
        g_W1p[idx] = W1[n * 513 + k];
    } else {
        int j = idx - N1C * K1C;
        if (j < N2C * K2C) {
            int n = j >> 10;       // /1024
            int k = j & 1023;
            g_W2p[j] = W2[n * 1025 + k];
        }
    }
}

// Prep: c vector + effective biases (t folded)
__global__ void prep_cbias(const float* __restrict__ t,
                           const float* __restrict__ W1, const float* __restrict__ b1,
                           const float* __restrict__ W2, const float* __restrict__ b2) {
    int j = blockIdx.x * 256 + threadIdx.x;
    float t0 = t[0];
    if (j < N1C) {
        const float* w1row = W1 + (size_t)j * 513;
        float s = 0.f;
        #pragma unroll 4
        for (int k = 0; k < K1C; k++)
            s += W2[(size_t)k * 1025 + j] * w1row[k];
        g_c[j] = s;
        g_beff1[j] = b1[j] + t0 * w1row[512];
    }
    if (j < N2C) {
        g_beff2[j] = b2[j] + t0 * W2[(size_t)j * 1025 + 1024];
    }
}

// ---------------------------------------------------------------------------
// Fused SGEMM, NT layout (A: MxK row-major, B: NxK row-major), C = A@B^T + bias
// PHASE 1: A = z,   B = W1p, out = relu(.) -> g_h
// PHASE 2: A = g_h, B = W2p, out = dz -> d_out; also trace (mask@c) -> dlogp
// Tile: 128x128x8, 256 threads, 8x8 per thread.
// ---------------------------------------------------------------------------
template<int PHASE>
__global__ void __launch_bounds__(256, 2)
sgemm_kernel(const float* __restrict__ Aparam, float* __restrict__ Outparam) {
    constexpr int K   = (PHASE == 1) ? K1C : K2C;
    constexpr int LDA = K;                  // dense
    constexpr int LDB = K;
    constexpr int LDC = (PHASE == 1) ? N1C : N2C;

    const float* A  = (PHASE == 1) ? Aparam : (const float*)g_h;
    const float* Bw = (PHASE == 1) ? (const float*)g_W1p : (const float*)g_W2p;
    float* outp     = (PHASE == 1) ? (float*)g_h : Outparam;

    __shared__ float As[8][128];
    __shared__ float Bs[8][128];

    const int tid  = threadIdx.x;
    const int m0   = blockIdx.y * 128;
    const int n0   = blockIdx.x * 128;

    // loader mapping: 2 threads per row, each one float4 along K
    const int lrow = tid >> 1;              // 0..127
    const int lk4  = (tid & 1) << 2;        // 0 or 4

    const float* Ap = A  + (size_t)(m0 + lrow) * LDA + lk4;
    const float* Bp = Bw + (size_t)(n0 + lrow) * LDB + lk4;

    const int tx = tid & 15;
    const int ty = tid >> 4;

    float acc[8][8];
    #pragma unroll
    for (int i = 0; i < 8; i++)
        #pragma unroll
        for (int j = 0; j < 8; j++) acc[i][j] = 0.f;

    // trace accumulator (PHASE 2, n-tile 0 only): mask(h) @ c along K
    float tr = 0.f;
    const bool do_trace = (PHASE == 2) && (blockIdx.x == 0);

    float4 av = *(const float4*)Ap;
    float4 bv = *(const float4*)Bp;

    for (int k0 = 0; k0 < K; k0 += 8) {
        As[lk4 + 0][lrow] = av.x;
        As[lk4 + 1][lrow] = av.y;
        As[lk4 + 2][lrow] = av.z;
        As[lk4 + 3][lrow] = av.w;
        Bs[lk4 + 0][lrow] = bv.x;
        Bs[lk4 + 1][lrow] = bv.y;
        Bs[lk4 + 2][lrow] = bv.z;
        Bs[lk4 + 3][lrow] = bv.w;

        if (do_trace) {
            const float4 cv = *(const float4*)(g_c + k0 + lk4);
            tr += (av.x > 0.f) ? cv.x : 0.f;
            tr += (av.y > 0.f) ? cv.y : 0.f;
            tr += (av.z > 0.f) ? cv.z : 0.f;
            tr += (av.w > 0.f) ? cv.w : 0.f;
        }

        __syncthreads();

        if (k0 + 8 < K) {   // prefetch next tiles into registers
            av = *(const float4*)(Ap + k0 + 8);
            bv = *(const float4*)(Bp + k0 + 8);
        }

        #pragma unroll
        for (int kk = 0; kk < 8; kk++) {
            float4 a0 = *(const float4*)&As[kk][ty * 4];
            float4 a1 = *(const float4*)&As[kk][ty * 4 + 64];
            float4 b0 = *(const float4*)&Bs[kk][tx * 4];
            float4 b1 = *(const float4*)&Bs[kk][tx * 4 + 64];
            float a[8] = {a0.x, a0.y, a0.z, a0.w, a1.x, a1.y, a1.z, a1.w};
            float b[8] = {b0.x, b0.y, b0.z, b0.w, b1.x, b1.y, b1.z, b1.w};
            #pragma unroll
            for (int i = 0; i < 8; i++)
                #pragma unroll
                for (int j = 0; j < 8; j++)
                    acc[i][j] += a[i] * b[j];
        }
        __syncthreads();
    }

    // ---------------- epilogue ----------------
    if (PHASE == 1) {
        const float4 be0 = *(const float4*)(g_beff1 + n0 + tx * 4);
        const float4 be1 = *(const float4*)(g_beff1 + n0 + 64 + tx * 4);
        #pragma unroll
        for (int i = 0; i < 8; i++) {
            int m = m0 + ty * 4 + (i & 3) + ((i >= 4) ? 64 : 0);
            float4 v0, v1;
            v0.x = fmaxf(acc[i][0] + be0.x, 0.f);
            v0.y = fmaxf(acc[i][1] + be0.y, 0.f);
            v0.z = fmaxf(acc[i][2] + be0.z, 0.f);
            v0.w = fmaxf(acc[i][3] + be0.w, 0.f);
            v1.x = fmaxf(acc[i][4] + be1.x, 0.f);
            v1.y = fmaxf(acc[i][5] + be1.y, 0.f);
            v1.z = fmaxf(acc[i][6] + be1.z, 0.f);
            v1.w = fmaxf(acc[i][7] + be1.w, 0.f);
            float* cp = outp + (size_t)m * LDC + n0 + tx * 4;
            *(float4*)cp        = v0;
            *(float4*)(cp + 64) = v1;
        }
    } else {
        const float4 be0 = *(const float4*)(g_beff2 + n0 + tx * 4);
        const float4 be1 = *(const float4*)(g_beff2 + n0 + 64 + tx * 4);
        #pragma unroll
        for (int i = 0; i < 8; i++) {
            int m = m0 + ty * 4 + (i & 3) + ((i >= 4) ? 64 : 0);
            float4 v0, v1;
            v0.x = acc[i][0] + be0.x;
            v0.y = acc[i][1] + be0.y;
            v0.z = acc[i][2] + be0.z;
            v0.w = acc[i][3] + be0.w;
            v1.x = acc[i][4] + be1.x;
            v1.y = acc[i][5] + be1.y;
            v1.z = acc[i][6] + be1.z;
            v1.w = acc[i][7] + be1.w;
            float* cp = outp + (size_t)m * LDC + n0 + tx * 4;
            *(float4*)cp        = v0;
            *(float4*)(cp + 64) = v1;
        }
        if (do_trace) {
            // each row's trace is split across its two loader threads (k%8 in
            // 0..3 vs 4..7); combine with a fixed-order shfl -> deterministic
            float tro = __shfl_xor_sync(0xffffffffu, tr, 1);
            if ((tid & 1) == 0) {
                float tot = tr + tro;
                outp[(size_t)NB * N2C + (m0 + lrow)] = -tot;
            }
        }
    }
}

// ---------------------------------------------------------------------------
extern "C" void kernel_launch(void* const* d_in, const int* in_sizes, int n_in,
                              void* d_out, int out_size) {
    const float* t  = (const float*)d_in[0];
    const float* z  = (const float*)d_in[1];
    // d_in[2] = logp_z (all zeros; unused by the math)
    const float* W1 = (const float*)d_in[3];
    const float* b1 = (const float*)d_in[4];
    const float* W2 = (const float*)d_in[5];
    const float* b2 = (const float*)d_in[6];
    float* out = (float*)d_out;   // layout: dz (NB*512) then dlogp (NB)

    // Prep (cheap, ~1M threads total)
    prep_pack<<<(N1C * K1C + N2C * K2C + 255) / 256, 256>>>(W1, W2);
    prep_cbias<<<4, 256>>>(t, W1, b1, W2, b2);

    // GEMM1: h = relu(z @ W1p^T + beff1) -> g_h
    {
        dim3 grid(N1C / 128, NB / 128);   // (8, 128)
        sgemm_kernel<1><<<grid, 256>>>(z, nullptr);
    }
    // GEMM2: dz = h @ W2p^T + beff2 -> out; dlogp = -(mask@c) -> out tail
    {
        dim3 grid(N2C / 128, NB / 128);   // (4, 128)
        sgemm_kernel<2><<<grid, 256>>>(nullptr, out);
    }
}